// round 9
// baseline (speedup 1.0000x reference)
#include <cuda_runtime.h>
#include <cuda_fp16.h>
#include <math.h>
#include <stdint.h>

#define NEXP 64
#define KSEL 8
#define DDIM 1024
#define MTILE 32
#define NCHUNK 32          // K chunks of 32 (2 mma k-steps of 16)
#define MAXBLK 1024
#define S11 2048.0f               // 2^11
#define I11 4.8828125e-4f         // 2^-11
#define STEP_STRIDE 1024          // words per k-step in Bfrag

__device__ float g_part[MAXBLK * NEXP];
// w pre-split into fp16 h/l planes, fragment-native order:
// word offset = (ch*2+step)*1024 + comp*512 + tile*64 + lane*2 + slot
__device__ uint32_t Bfrag[NCHUNK * 2 * 2 * 8 * 64];

__device__ __forceinline__ uint32_t h2u(half2 h) {
    return *reinterpret_cast<uint32_t*>(&h);
}

// 2-level split: v = h + l*2^-11 + r, |r| ~ 2^-24 |v|
__device__ __forceinline__ void split2(float2 v, uint32_t& h, uint32_t& l) {
    half2 hh = __float22half2_rn(v);
    float2 hb = __half22float2(hh);
    half2 ll = __float22half2_rn(
        make_float2((v.x - hb.x) * S11, (v.y - hb.y) * S11));
    h = h2u(hh);
    l = h2u(ll);
}

// chained accumulate (only for 2^-11-scaled correction chains)
#define MMA_F16_ACC(cc, a, b0, b1)                                             \
    asm volatile(                                                              \
        "mma.sync.aligned.m16n8k16.row.col.f32.f16.f16.f32 "                   \
        "{%0,%1,%2,%3},{%4,%5,%6,%7},{%8,%9},{%0,%1,%2,%3};"                   \
        : "+f"((cc)[0]), "+f"((cc)[1]), "+f"((cc)[2]), "+f"((cc)[3])           \
        : "r"((a)[0]), "r"((a)[1]), "r"((a)[2]), "r"((a)[3]),                  \
          "r"(b0), "r"(b1))

// fresh accumulator: D = A*B + 0 — avoids tensor-core RZ accumulation bias
#define MMA_F16_NEW(dd, a, b0, b1)                                             \
    asm volatile(                                                              \
        "mma.sync.aligned.m16n8k16.row.col.f32.f16.f16.f32 "                   \
        "{%0,%1,%2,%3},{%4,%5,%6,%7},{%8,%9},{%10,%11,%12,%13};"               \
        : "=f"((dd)[0]), "=f"((dd)[1]), "=f"((dd)[2]), "=f"((dd)[3])           \
        : "r"((a)[0]), "r"((a)[1]), "r"((a)[2]), "r"((a)[3]),                  \
          "r"(b0), "r"(b1),                                                    \
          "f"(0.0f), "f"(0.0f), "f"(0.0f), "f"(0.0f))

// ---- precompute: split w into Bfrag (fragment-native, h/l planes) ----
__global__ void wsplit_kernel(const float* __restrict__ w)
{
    int idx = blockIdx.x * 256 + threadIdx.x;    // 0..32767 = (n, kpair)
    int n = idx >> 9;                            // expert
    int kp = idx & 511;                          // k/2
    float2 v = *(const float2*)(w + (size_t)n * DDIM + kp * 2);
    uint32_t h, l;
    split2(v, h, l);
    int k = kp * 2;
    int ch = k >> 5, win = k & 31;
    int s = win >> 4, kk = win & 15;
    int sl = kk >> 3, q = (kk & 7) >> 1;
    int tile = n >> 3, lane = (n & 7) * 4 + q;
    uint32_t base = (uint32_t)(ch * 2 + s) * STEP_STRIDE + tile * 64 + lane * 2 + sl;
    Bfrag[base]       = h;   // comp 0 (h plane)
    Bfrag[base + 512] = l;   // comp 1 (l plane), comp stride = 8*64
}

__global__ void __launch_bounds__(128, 4) gate_kernel(
    const float* __restrict__ x,
    const float* __restrict__ nw, const float* __restrict__ noise,
    float* __restrict__ out_w, float* __restrict__ out_ids)
{
    __shared__ __align__(16) float U[MTILE * 65];  // epilogue canvas
    __shared__ float nw_s[NEXP];
    __shared__ float wsumS[NEXP];

    const int tid    = threadIdx.x;
    const int wid    = tid >> 5;        // 0..3
    const int lane   = tid & 31;
    const int quad   = lane & 3;
    const int r0     = lane >> 2;
    const int rowgrp = wid >> 1;        // 0..1 -> rows rowgrp*16..+15
    const int eg     = wid & 1;         // expert half: tiles eg*4..eg*4+3
    const int base   = blockIdx.x * MTILE;

    if (tid < NEXP) nw_s[tid] = nw[tid];

    const float* pA  = x + (size_t)(base + rowgrp * 16 + r0) * DDIM + quad * 2;
    const float* pA8 = pA + 8 * DDIM;
    const uint32_t* const Bp = Bfrag + (uint32_t)(eg * 4) * 64 + lane * 2;

    float c0[4][4], c1a[4][4], c1b[4][4];
#pragma unroll
    for (int t = 0; t < 4; t++)
#pragma unroll
        for (int i = 0; i < 4; i++) {
            c0[t][i] = 0.f; c1a[t][i] = 0.f; c1b[t][i] = 0.f;
        }

// Raw A chunk: per kstep s, 4 float2 pairs in fragment order
#define LDA(ch, a) do {                                                        \
    _Pragma("unroll")                                                          \
    for (int _s2 = 0; _s2 < 2; _s2++) {                                        \
        *(float2*)&(a)[_s2 * 8 + 0] = *(const float2*)(pA  + (ch) * 32 + _s2 * 16);     \
        *(float2*)&(a)[_s2 * 8 + 2] = *(const float2*)(pA8 + (ch) * 32 + _s2 * 16);     \
        *(float2*)&(a)[_s2 * 8 + 4] = *(const float2*)(pA  + (ch) * 32 + _s2 * 16 + 8); \
        *(float2*)&(a)[_s2 * 8 + 6] = *(const float2*)(pA8 + (ch) * 32 + _s2 * 16 + 8); \
    }                                                                          \
} while (0)

// Two-tile group: all MMAs independent (no back-to-back same-accumulator RAW);
// NEW -> fold distance = 4 MMA issues.
#define TILE_PAIR(bp, t0, t1, ah, al) do {                                     \
    uint2 bh0 = *(const uint2*)((bp) + (t0) * 64);                             \
    uint2 bl0 = *(const uint2*)((bp) + (t0) * 64 + 512);                       \
    uint2 bh1 = *(const uint2*)((bp) + (t1) * 64);                             \
    uint2 bl1 = *(const uint2*)((bp) + (t1) * 64 + 512);                       \
    float dd0[4], dd1[4];                                                      \
    MMA_F16_NEW(dd0, ah, bh0.x, bh0.y);                                        \
    MMA_F16_NEW(dd1, ah, bh1.x, bh1.y);                                        \
    MMA_F16_ACC(c1a[t0], ah, bl0.x, bl0.y);                                    \
    MMA_F16_ACC(c1a[t1], ah, bl1.x, bl1.y);                                    \
    MMA_F16_ACC(c1b[t0], al, bh0.x, bh0.y);                                    \
    MMA_F16_ACC(c1b[t1], al, bh1.x, bh1.y);                                    \
    c0[t0][0] += dd0[0]; c0[t0][1] += dd0[1];                                  \
    c0[t0][2] += dd0[2]; c0[t0][3] += dd0[3];                                  \
    c0[t1][0] += dd1[0]; c0[t1][1] += dd1[1];                                  \
    c0[t1][2] += dd1[2]; c0[t1][3] += dd1[3];                                  \
} while (0)

#define CHUNK_BODY(ch, aC, aN) do {                                            \
    if ((ch) + 1 < NCHUNK) LDA((ch) + 1, aN);                                  \
    _Pragma("unroll")                                                          \
    for (int _s = 0; _s < 2; _s++) {                                           \
        uint32_t ah[4], al[4];                                                 \
        _Pragma("unroll")                                                      \
        for (int _i = 0; _i < 4; _i++)                                         \
            split2(*(float2*)&(aC)[_s * 8 + _i * 2], ah[_i], al[_i]);          \
        const uint32_t* bp = Bp + ((uint32_t)(ch) * 2 + _s) * STEP_STRIDE;     \
        TILE_PAIR(bp, 0, 1, ah, al);                                           \
        TILE_PAIR(bp, 2, 3, ah, al);                                           \
    }                                                                          \
} while (0)

    // ---- main loop: no smem, no barriers; ping-pong A in registers ----
    float aCur[16], aNxt[16];
    LDA(0, aCur);
#pragma unroll 1
    for (int cc = 0; cc < NCHUNK; cc += 2) {
        CHUNK_BODY(cc, aCur, aNxt);
        CHUNK_BODY(cc + 1, aNxt, aCur);
    }

    // ---- combine levels, dump to L[32][65] ----
    {
        int rA = rowgrp * 16 + r0;
#pragma unroll
        for (int t = 0; t < 4; t++) {
            int cb = (eg * 4 + t) * 8 + 2 * quad;
#pragma unroll
            for (int i = 0; i < 4; i++) {
                float v = fmaf(c1a[t][i] + c1b[t][i], I11, c0[t][i]);
                int rr = rA + (i >> 1) * 8;
                U[rr * 65 + cb + (i & 1)] = v;
            }
        }
    }
    __syncthreads();

    // ---- epilogue: warp 0, one row per lane ----
    if (tid < 32) {
        const int r = tid;
        float L[64];
#pragma unroll
        for (int e = 0; e < 64; e++) L[e] = U[r * 65 + e];

        float m = -INFINITY;
#pragma unroll
        for (int e = 0; e < 64; e++) m = fmaxf(m, L[e]);
        float s = 0.f;
#pragma unroll
        for (int e = 0; e < 64; e++) s += __expf(L[e] - m);
        float sinv = 1.f / s;

        // per-expert column sums over all 32 rows (deterministic)
#pragma unroll
        for (int e = 0; e < 64; e++) {
            float v = __expf(L[e] - m) * sinv;
            v += __shfl_xor_sync(0xffffffffu, v, 16);
            v += __shfl_xor_sync(0xffffffffu, v, 8);
            v += __shfl_xor_sync(0xffffffffu, v, 4);
            v += __shfl_xor_sync(0xffffffffu, v, 2);
            v += __shfl_xor_sync(0xffffffffu, v, 1);
            if ((e & 31) == lane) wsumS[e] = v;
        }

        // noisy logits
        const float4* np = (const float4*)(noise + (size_t)(base + r) * NEXP);
#pragma unroll
        for (int q = 0; q < 16; q++) {
            float4 nv = np[q];
            L[q * 4 + 0] = fmaf(nv.x, nw_s[q * 4 + 0], L[q * 4 + 0]);
            L[q * 4 + 1] = fmaf(nv.y, nw_s[q * 4 + 1], L[q * 4 + 1]);
            L[q * 4 + 2] = fmaf(nv.z, nw_s[q * 4 + 2], L[q * 4 + 2]);
            L[q * 4 + 3] = fmaf(nv.w, nw_s[q * 4 + 3], L[q * 4 + 3]);
        }

        // top-8 (strict >, lowest index wins ties)
        float best[KSEL];
        int bid[KSEL];
        unsigned long long used = 0ull;
#pragma unroll
        for (int k = 0; k < KSEL; k++) {
            float mv = -INFINITY;
            int mi = 0;
#pragma unroll
            for (int e = 0; e < 64; e++) {
                bool ok = !((used >> e) & 1ull);
                if (ok && L[e] > mv) { mv = L[e]; mi = e; }
            }
            used |= 1ull << mi;
            best[k] = mv;
            bid[k] = mi;
        }
        float m0 = best[0];
        float ss = 0.f;
#pragma unroll
        for (int k = 0; k < KSEL; k++) ss += __expf(best[k] - m0);
        float inv = 1.f / ss;

        float4 z = {0.f, 0.f, 0.f, 0.f};
        float4* ow = (float4*)(out_w + (size_t)(base + r) * NEXP);
#pragma unroll
        for (int q = 0; q < 16; q++) ow[q] = z;
#pragma unroll
        for (int k = 0; k < KSEL; k++) {
            out_w[(size_t)(base + r) * NEXP + bid[k]] = __expf(best[k] - m0) * inv;
            out_ids[(size_t)(base + r) * KSEL + k] = (float)bid[k];
        }
    }
    __syncthreads();
    if (tid < NEXP)
        g_part[blockIdx.x * NEXP + tid] = wsumS[tid];
}

__global__ void __launch_bounds__(1024) loss_kernel(
    int nBlocks, int N, float* __restrict__ out_loss)
{
    __shared__ double red[1024];
    const int t = threadIdx.x;
    const int e = t & 63, g = t >> 6;  // 16 partials per expert
    double s = 0.0;
    for (int b = g; b < nBlocks; b += 16) s += (double)g_part[b * NEXP + e];
    red[t] = s;
    __syncthreads();
    for (int off = 512; off >= 64; off >>= 1) {
        if (t < off) red[t] += red[t + off];
        __syncthreads();
    }
    if (t < 64) {
        double d = red[t] / (double)N - 1.0 / 64.0;
        red[t] = d * d;
    }
    __syncthreads();
    for (int off = 32; off >= 1; off >>= 1) {
        if (t < off) red[t] += red[t + off];
        __syncthreads();
    }
    if (t == 0) *out_loss = (float)(red[0] / 64.0 * 0.01);
}

extern "C" void kernel_launch(void* const* d_in, const int* in_sizes, int n_in,
                              void* d_out, int out_size)
{
    const float* x     = (const float*)d_in[0];  // [N, 1024]
    const float* w     = (const float*)d_in[1];  // [64, 1024]
    const float* nw    = (const float*)d_in[2];  // [64]
    const float* noise = (const float*)d_in[3];  // [N, 64]

    int N = in_sizes[3] / NEXP;
    int nBlocks = N / MTILE;

    float* out      = (float*)d_out;
    float* out_w    = out;                                        // [N, 64]
    float* out_ids  = out + (size_t)N * NEXP;                     // [N, 8]
    float* out_loss = out + (size_t)N * NEXP + (size_t)N * KSEL;  // [1]

    wsplit_kernel<<<128, 256>>>(w);
    gate_kernel<<<nBlocks, 128>>>(x, nw, noise, out_w, out_ids);
    loss_kernel<<<1, 1024>>>(nBlocks, N, out_loss);
}